// round 17
// baseline (speedup 1.0000x reference)
#include <cuda_runtime.h>
#include <math.h>

// ---------------------------------------------------------------------------
// PrettyPCF, R17: global binning kernel + prologue-free main kernel.
//  * K1 (1 block, 512 thr): counting-sort all 1536 B points into a 5x5 cell
//    grid in GLOBAL memory (12KB -> L1/L2 resident for K2). Done ONCE,
//    removing the per-block binning prologue that sat on every block's
//    critical path in R14-R16.
//  * K2 (1536 blocks x 96 thr): block = one i-point, 3 row-warps.
//    - warp 0 computes the weight pair table (once per i, no duplication)
//    - each warp ballot-compacts one neighbor cell-row's survivors (read
//      directly from the sorted global array via __ldg) into a small
//      shared queue
//    - balanced drain: all 3 warps x all 3 queues, uniform weights
//    - only 2 block barriers, 96 threads wide.
//  * Proven pieces: rcp/ex2 approx, polynomial acos/atan2, lane==bin
//    register accumulators, done-counter finalize + state reset.
// ---------------------------------------------------------------------------

#define NPTS   1536
#define NBINS  50
#define G      5                   // grid cells per side (cell = 0.2)
#define NCELL  (G * G)             // 25
#define ZC     1.2f

#define K1_THR 512
#define K1_PPT (NPTS / K1_THR)     // 3

#define NWARP  3                   // row-warps per block (one i)
#define NTHR   (NWARP * 32)        // 96
#define NBLK   NPTS                // 1536 blocks
#define QW     320                 // per-warp queue capacity (row max ~250)

#define RMAX_D (2.0 * sqrt(1.0 / (2.0 * sqrt(3.0) * 1536.0)))

__device__ float2 g_sbp[NPTS];           // sorted B points (u-units)
__device__ unsigned short g_sbj[NPTS];   // original j index
__device__ int    g_cellstart[NCELL + 1];
__device__ float  g_acc[NBINS];          // zero-init; reset by last block
__device__ int    g_done;

__device__ __forceinline__ float ex2_fast(float x) {
    float y;
    asm("ex2.approx.ftz.f32 %0, %1;" : "=f"(y) : "f"(x));
    return y;
}
__device__ __forceinline__ float rcp_fast(float x) {
    float y;
    asm("rcp.approx.ftz.f32 %0, %1;" : "=f"(y) : "f"(x));
    return y;
}

// acos(x), x in [0,1]; abs err < 6.7e-5 (A&S 4.4.45). acos(1) = 0 exactly.
__device__ __forceinline__ float acos_poly(float x) {
    float p = fmaf(x, fmaf(x, fmaf(x, -0.0187293f, 0.0742610f),
                               -0.2121144f), 1.5707288f);
    return sqrtf(1.0f - x) * p;
}

// atan(r), r in [0,1]; minimax odd poly, abs err ~1e-6.
__device__ __forceinline__ float atan_poly(float r) {
    float r2 = r * r;
    float p = fmaf(r2, fmaf(r2, fmaf(r2, fmaf(r2, fmaf(r2,
              -0.0117212f, 0.05265332f), -0.11643287f),
               0.19354346f), -0.33262347f), 0.99997726f);
    return r * p;
}

// atan2(y, x) for x,y >= 0 (first quadrant), branchless, rcp-based.
__device__ __forceinline__ float atan2_q1(float y, float x) {
    float mn = fminf(x, y);
    float mx = fmaxf(x, y);
    float r  = mn * rcp_fast(fmaxf(mx, 1e-20f));
    float a  = atan_poly(r);
    return (y > x) ? (1.5707963268f - a) : a;
}

// ---------------------------------------------------------------------------
// K1: counting sort of B into g_sbp/g_sbj/g_cellstart (one block)
// ---------------------------------------------------------------------------
__global__ __launch_bounds__(K1_THR)
void bin_kernel(const float* __restrict__ B)
{
    __shared__ int scnt[NCELL];
    __shared__ int sstart[NCELL + 1];

    const int tid  = threadIdx.x;
    const int lane = tid & 31;
    const float invR = (float)(1.0 / RMAX_D);

    if (tid < NCELL) scnt[tid] = 0;
    __syncthreads();

    float xs[K1_PPT], ys[K1_PPT];
    int   cs[K1_PPT];
#pragma unroll
    for (int k = 0; k < K1_PPT; k++) {
        int j = tid + k * K1_THR;
        float x = B[3 * j];
        float y = B[3 * j + 1];
        int cx = min(G - 1, (int)(x * (float)G));
        int cy = min(G - 1, (int)(y * (float)G));
        cs[k] = cy * G + cx;
        xs[k] = x * invR;
        ys[k] = y * invR;
        atomicAdd(&scnt[cs[k]], 1);
    }
    __syncthreads();

    if (tid < 32) {                       // warp 0: exclusive scan (25 vals)
        int c = (lane < NCELL) ? scnt[lane] : 0;
#pragma unroll
        for (int off = 1; off < 32; off <<= 1) {
            int n = __shfl_up_sync(0xFFFFFFFFu, c, off);
            if (lane >= off) c += n;
        }
        if (lane < NCELL) sstart[lane + 1] = c;
        if (lane == 0)    sstart[0] = 0;
        if (lane < NCELL) scnt[lane] = 0;  // reuse as scatter cursor
    }
    __syncthreads();

    if (tid < NCELL + 1) g_cellstart[tid] = sstart[tid];

#pragma unroll
    for (int k = 0; k < K1_PPT; k++) {
        int c = cs[k];
        int slot = sstart[c] + atomicAdd(&scnt[c], 1);
        g_sbp[slot] = make_float2(xs[k], ys[k]);
        g_sbj[slot] = (unsigned short)(tid + k * K1_THR);
    }
}

// ---------------------------------------------------------------------------
// K2: warp-per-(i,row), prologue-free, balanced drain
// ---------------------------------------------------------------------------
__global__ __launch_bounds__(NTHR)
void pcf_kernel(const float* __restrict__ A, const int* __restrict__ scp,
                float* __restrict__ out)
{
    __shared__ float  swq[NWARP * QW];   // per-warp survivor u's
    __shared__ int    scnt_w[NWARP];
    __shared__ float2 sw12[32];          // (w1,w2) per lane for this i
    __shared__ float  sacc[NBINS];
    __shared__ int    is_last;

    const int tid  = threadIdx.x;
    const int lane = tid & 31;
    const int wid  = tid >> 5;           // sub-row 0..2
    const int i    = blockIdx.x;
    float* wq = &swq[wid * QW];

    const float invR = (float)(1.0 / RMAX_D);
    const float ax = A[3 * i];
    const float ay = A[3 * i + 1];
    const float axs = ax * invR;
    const float ays = ay * invR;

    if (tid < NBINS) sacc[tid] = 0.0f;

    // ---- warp 0: weight pair table for this i ----
    if (wid == 0) {
        const float TWO_PI = 6.2831853071795864769f;
        const float ex0 = ax,  ex1 = 1.0f - ax;
        const float ex2v = ay, ex3 = 1.0f - ay;
        const float mEdge = fminf(fminf(ex0, ex1), fminf(ex2v, ex3));
        const float rsMax = (float)(5.0 * RMAX_D);
        float w1 = 1.0f, w2 = 1.0f;
        if (mEdge < rsMax) {             // warp-uniform: i near a border
            float aval = 0.0f;
            if (lane < 8) {
                int e     = lane >> 1;
                int which = lane & 1;
                float exk = (e == 0) ? ax : (e == 1) ? (1.0f - ax)
                          : (e == 2) ? ay : (1.0f - ay);
                float eyk = (e < 2) ? ay : ax;
                float yy  = which ? (1.0f - eyk) : eyk;
                aval = atan2_q1(yy, exk);
            }
            const float a10 = __shfl_sync(0xFFFFFFFFu, aval, 0);
            const float a20 = __shfl_sync(0xFFFFFFFFu, aval, 1);
            const float a11 = __shfl_sync(0xFFFFFFFFu, aval, 2);
            const float a21 = __shfl_sync(0xFFFFFFFFu, aval, 3);
            const float a12 = __shfl_sync(0xFFFFFFFFu, aval, 4);
            const float a22 = __shfl_sync(0xFFFFFFFFu, aval, 5);
            const float a13 = __shfl_sync(0xFFFFFFFFu, aval, 6);
            const float a23 = __shfl_sync(0xFFFFFFFFu, aval, 7);

            const float rs1 = (float)((lane +  1) * (5.0 / 50.0) * RMAX_D);
            const float rs2 = (float)((lane + 33) * (5.0 / 50.0) * RMAX_D);
            {
                float ir = rcp_fast(rs1);
                float al0 = acos_poly(fminf(ex0  * ir, 1.0f));
                float al1 = acos_poly(fminf(ex1  * ir, 1.0f));
                float al2 = acos_poly(fminf(ex2v * ir, 1.0f));
                float al3 = acos_poly(fminf(ex3  * ir, 1.0f));
                float full = TWO_PI
                    - (fminf(al0, a10) + fminf(al0, a20))
                    - (fminf(al1, a11) + fminf(al1, a21))
                    - (fminf(al2, a12) + fminf(al2, a22))
                    - (fminf(al3, a13) + fminf(al3, a23));
                float per = fminf(fmaxf(full * (1.0f / TWO_PI), 0.0f), 1.0f);
                w1 = fminf(rcp_fast(fmaxf(per, 1e-9f)), 4.0f);
            }
            {
                float ir = rcp_fast(rs2);
                float al0 = acos_poly(fminf(ex0  * ir, 1.0f));
                float al1 = acos_poly(fminf(ex1  * ir, 1.0f));
                float al2 = acos_poly(fminf(ex2v * ir, 1.0f));
                float al3 = acos_poly(fminf(ex3  * ir, 1.0f));
                float full = TWO_PI
                    - (fminf(al0, a10) + fminf(al0, a20))
                    - (fminf(al1, a11) + fminf(al1, a21))
                    - (fminf(al2, a12) + fminf(al2, a22))
                    - (fminf(al3, a13) + fminf(al3, a23));
                float per = fminf(fmaxf(full * (1.0f / TWO_PI), 0.0f), 1.0f);
                w2 = fminf(rcp_fast(fmaxf(per, 1e-9f)), 4.0f);
            }
        }
        if (lane >= NBINS - 32) w2 = 0.0f;   // dead bins contribute 0
        sw12[lane] = make_float2(w1, w2);
    }

    // ---- Phase A: scan this warp's neighbor cell-row (global sorted) ----
    const int   same = *scp;
    const float cut2 = (5.0f + ZC) * (5.0f + ZC);   // u-units

    int cix = min(G - 1, (int)(ax * (float)G));
    int ciy = min(G - 1, (int)(ay * (float)G));
    int cxlo = max(cix - 1, 0), cxhi = min(cix + 1, G - 1);
    int cylo = max(ciy - 1, 0), cyhi = min(ciy + 1, G - 1);
    int r    = cylo + wid;

    int cnt = 0;
    if (r <= cyhi) {
        int lo = __ldg(&g_cellstart[r * G + cxlo]);
        int hi = __ldg(&g_cellstart[r * G + cxhi + 1]);
        const unsigned lt_mask = (1u << lane) - 1u;
        for (int base = lo; base < hi; base += 32) {
            int jl = base + lane;
            int jc = min(jl, NPTS - 1);
            float2 p = __ldg(&g_sbp[jc]);
            float dx = axs - p.x;
            float dy = ays - p.y;
            float d2 = fmaf(dx, dx, dy * dy);
            bool pred = (jl < hi) && (d2 < cut2)
                        && !(same && i == (int)__ldg(&g_sbj[jc]));
            unsigned mask = __ballot_sync(0xFFFFFFFFu, pred);
            if (pred) {
                int slot = cnt + __popc(mask & lt_mask);
                if (slot < QW) wq[slot] = sqrtf(d2);   // u = d/RMAX
            }
            cnt += __popc(mask);
        }
        if (cnt > QW) cnt = QW;
    }
    if (lane == 0) scnt_w[wid] = cnt;
    __syncthreads();   // queues + counts + sw12 + sacc ready

    // ---- Phase B: all 3 warps drain all 3 queues (balanced) ----
    const float L2E = 1.4426950408889634f;
    const float c2  = -16.0f * L2E;
    const float zb1 = 0.1f * (float)(lane + 1);
    const float zb2 = zb1 + 3.2f;
    const float c1a = 32.0f * zb1 * L2E;
    const float c0a = -16.0f * zb1 * zb1 * L2E;
    const float c1b = 32.0f * zb2 * L2E;
    const float c0b = -16.0f * zb2 * zb2 * L2E;

    const float2 ww = sw12[lane];        // same weights for all 3 queues
    float acc1 = 0.0f, acc2 = 0.0f;
#pragma unroll
    for (int q = 0; q < NWARP; q++) {
        const float* qq = &swq[q * QW];
        const int n = scnt_w[q];
        int e = wid;
        for (; e + NWARP < n; e += 2 * NWARP) {
            float uA  = qq[e];
            float uB  = qq[e + NWARP];
            float uA2 = uA * uA;
            float uB2 = uB * uB;
            float gA1 = ex2_fast(fmaf(c2, uA2, fmaf(c1a, uA, c0a)));
            float gB1 = ex2_fast(fmaf(c2, uB2, fmaf(c1a, uB, c0a)));
            float gA2 = ex2_fast(fmaf(c2, uA2, fmaf(c1b, uA, c0b)));
            float gB2 = ex2_fast(fmaf(c2, uB2, fmaf(c1b, uB, c0b)));
            acc1 = fmaf(gA1, ww.x, acc1);
            acc1 = fmaf(gB1, ww.x, acc1);
            acc2 = fmaf(gA2, ww.y, acc2);
            acc2 = fmaf(gB2, ww.y, acc2);
        }
        if (e < n) {
            float u  = qq[e];
            float u2 = u * u;
            acc1 = fmaf(ex2_fast(fmaf(c2, u2, fmaf(c1a, u, c0a))), ww.x, acc1);
            acc2 = fmaf(ex2_fast(fmaf(c2, u2, fmaf(c1b, u, c0b))), ww.y, acc2);
        }
    }

    // ---- Block reduction -> global ----
    atomicAdd(&sacc[lane], acc1);
    if (lane < NBINS - 32) atomicAdd(&sacc[lane + 32], acc2);
    __syncthreads();
    if (tid < NBINS) atomicAdd(&g_acc[tid], sacc[tid]);

    // ---- Last block finalizes ----
    __threadfence();
    if (tid == 0) {
        int v = atomicAdd(&g_done, 1);
        is_last = (v == NBLK - 1);
    }
    __syncthreads();
    if (is_last) {
        if (tid < NBINS) {
            int b = tid;
            double rs_d  = (b + 1) * (5.0 / 50.0) * RMAX_D;
            double inner = fmax(0.0, rs_d - 0.5 * RMAX_D);
            double outer = rs_d + 0.5 * RMAX_D;
            float  area  = (float)(M_PI * (outer * outer - inner * inner));
            const float GF = (float)(1.0 / (sqrt(M_PI) * 0.25));

            float s   = g_acc[b] * GF;
            float pcf = s / 1536.0f / (area * 1536.0f);

            out[2 * b]     = (float)rs_d / (float)RMAX_D;
            out[2 * b + 1] = pcf;

            g_acc[b] = 0.0f;          // reset for next graph replay
        }
        if (tid == 0) g_done = 0;
    }
}

// ---------------------------------------------------------------------------
extern "C" void kernel_launch(void* const* d_in, const int* in_sizes, int n_in,
                              void* d_out, int out_size)
{
    const float* A  = (const float*)d_in[0];   // disks_a [1536,3]
    const float* B  = (const float*)d_in[1];   // disks_b [1536,3]
    const int*   sc = (const int*)d_in[2];     // same_category scalar
    float* out = (float*)d_out;

    bin_kernel<<<1, K1_THR>>>(B);
    pcf_kernel<<<NBLK, NTHR>>>(A, sc, out);
}